// round 1
// baseline (speedup 1.0000x reference)
#include <cuda_runtime.h>

// Problem constants
#define IMGS   128      // BS*T
#define CH     256      // z channels
#define EMB    256
#define HW     256      // H*W
#define NPIX   32768    // IMGS*HW
#define VOCAB  4096

// Output region offsets (elements) in d_out:
//   z:      [0,        8388608)
//   zq:     [8388608, 16777216)
//   recon:  [16777216, 25165824)
//   tokens: [25165824, 25198592)

__device__ unsigned long long g_packed[NPIX];
__device__ float g_csq[VOCAB];
__device__ float g_zsq[NPIX];
__device__ int   g_tok[NPIX];

__device__ __forceinline__ unsigned int f2ord(float f) {
    unsigned int u = __float_as_uint(f);
    return (u & 0x80000000u) ? ~u : (u | 0x80000000u);
}

// ---------------------------------------------------------------------------
// Init: codebook squared norms (one warp per row) + packed argmin buffer reset
// ---------------------------------------------------------------------------
__global__ void k_init(const float* __restrict__ cb) {
    int t = threadIdx.x;
    int gt = blockIdx.x * 128 + t;
    if (gt < NPIX) g_packed[gt] = ~0ull;

    int r = blockIdx.x * 4 + (t >> 5);   // 1024 blocks * 4 warps = 4096 rows
    int lane = t & 31;
    if (r < VOCAB) {
        const float* row = cb + r * EMB;
        float s = 0.f;
        #pragma unroll 4
        for (int e = lane; e < EMB; e += 32) { float v = row[e]; s += v * v; }
        #pragma unroll
        for (int o = 16; o; o >>= 1) s += __shfl_down_sync(0xFFFFFFFFu, s, o);
        if (lane == 0) g_csq[r] = s;
    }
}

// ---------------------------------------------------------------------------
// 256x256x256 per-image GEMM: Out[m,n] = sum_k W[m,k]*xf(In[k,n]) + bias[m]
// XFORM: input transform 2x-1 (pre-quantize path)
// Block: 64x64 tile, 256 threads, 4x4 microtile, K-chunk 16
// ---------------------------------------------------------------------------
template<bool XFORM>
__global__ void __launch_bounds__(256) k_gemm256(
    const float* __restrict__ W, const float* __restrict__ bias,
    const float* __restrict__ In, float* __restrict__ Out)
{
    __shared__ float Ws[16][68];   // [k][m], padded
    __shared__ float Bs[16][64];   // [k][n]
    const int img = blockIdx.z;
    const int m0 = blockIdx.y * 64, n0 = blockIdx.x * 64;
    const float* in = In + (size_t)img * 65536;
    float* out = Out + (size_t)img * 65536;
    const int t = threadIdx.x;
    const int ty = t >> 4, tx = t & 15;

    float acc[4][4] = {};

    for (int k0 = 0; k0 < 256; k0 += 16) {
        {   // W tile 64 rows x 16 k
            int row = t >> 2;
            int c4  = (t & 3) * 4;
            float4 w4 = *reinterpret_cast<const float4*>(&W[(m0 + row) * 256 + k0 + c4]);
            Ws[c4 + 0][row] = w4.x; Ws[c4 + 1][row] = w4.y;
            Ws[c4 + 2][row] = w4.z; Ws[c4 + 3][row] = w4.w;
        }
        {   // B tile 16 k x 64 n
            int kk = t >> 4;
            int n4 = (t & 15) * 4;
            float4 b4 = *reinterpret_cast<const float4*>(&in[(k0 + kk) * 256 + n0 + n4]);
            if (XFORM) {
                b4.x = 2.f * b4.x - 1.f; b4.y = 2.f * b4.y - 1.f;
                b4.z = 2.f * b4.z - 1.f; b4.w = 2.f * b4.w - 1.f;
            }
            *reinterpret_cast<float4*>(&Bs[kk][n4]) = b4;
        }
        __syncthreads();
        #pragma unroll
        for (int kk = 0; kk < 16; kk++) {
            float a[4], b[4];
            *reinterpret_cast<float4*>(a) = *reinterpret_cast<float4*>(&Ws[kk][ty * 4]);
            *reinterpret_cast<float4*>(b) = *reinterpret_cast<float4*>(&Bs[kk][tx * 4]);
            #pragma unroll
            for (int i = 0; i < 4; i++)
                #pragma unroll
                for (int j = 0; j < 4; j++)
                    acc[i][j] += a[i] * b[j];
        }
        __syncthreads();
    }

    #pragma unroll
    for (int i = 0; i < 4; i++) {
        int m = m0 + ty * 4 + i;
        float bm = bias[m];
        float4 o;
        o.x = acc[i][0] + bm; o.y = acc[i][1] + bm;
        o.z = acc[i][2] + bm; o.w = acc[i][3] + bm;
        *reinterpret_cast<float4*>(&out[m * 256 + n0 + tx * 4]) = o;
    }
}

// ---------------------------------------------------------------------------
// z squared norms per pixel (deterministic sequential sum over e)
// ---------------------------------------------------------------------------
__global__ void k_zsq(const float* __restrict__ z) {
    int img = blockIdx.x;
    int hw = threadIdx.x;
    const float* p = z + (size_t)img * 65536 + hw;
    float s = 0.f;
    #pragma unroll 8
    for (int e = 0; e < 256; e++) { float v = p[e * 256]; s += v * v; }
    g_zsq[img * 256 + hw] = s;
}

// ---------------------------------------------------------------------------
// Distance GEMM + fused argmin: D[v,n] = (zsq[n]+csq[v]) - 2*dot(C[v],Z[:,n])
// Block: 128(v) x 128(n), 256 threads, 8x8 microtile, K-chunk 8.
// Min reduced via packed (ordered-dist<<32 | idx) -> shared -> global atomicMin.
// ---------------------------------------------------------------------------
__global__ void __launch_bounds__(256) k_dist(
    const float* __restrict__ cb, const float* __restrict__ z)
{
    __shared__ float As[8][132];   // [e][v], padded
    __shared__ float Bs[8][128];   // [e][n]
    __shared__ unsigned long long red[128];

    const int v0 = blockIdx.y * 128;
    const int n0 = blockIdx.x * 128;
    // pixel n = img*256 + hw ; z stored [img][e][hw] ; tile lives in one image
    const float* zb = z + (size_t)(n0 >> 8) * 65536 + (n0 & 255);
    const int t = threadIdx.x;
    const int ty = t >> 4, tx = t & 15;

    if (t < 128) red[t] = ~0ull;

    float acc[8][8] = {};

    for (int e0 = 0; e0 < 256; e0 += 8) {
        {   // codebook tile: 128 v x 8 e
            int v = t >> 1;
            int e4 = (t & 1) * 4;
            float4 a4 = *reinterpret_cast<const float4*>(&cb[(v0 + v) * 256 + e0 + e4]);
            As[e4 + 0][v] = a4.x; As[e4 + 1][v] = a4.y;
            As[e4 + 2][v] = a4.z; As[e4 + 3][v] = a4.w;
        }
        {   // z tile: 8 e x 128 n
            int e = t >> 5;
            int n4 = (t & 31) * 4;
            float4 b4 = *reinterpret_cast<const float4*>(&zb[(e0 + e) * 256 + n4]);
            *reinterpret_cast<float4*>(&Bs[e][n4]) = b4;
        }
        __syncthreads();
        #pragma unroll
        for (int k = 0; k < 8; k++) {
            float a[8], b[8];
            *reinterpret_cast<float4*>(a)     = *reinterpret_cast<float4*>(&As[k][ty * 8]);
            *reinterpret_cast<float4*>(a + 4) = *reinterpret_cast<float4*>(&As[k][ty * 8 + 4]);
            *reinterpret_cast<float4*>(b)     = *reinterpret_cast<float4*>(&Bs[k][tx * 8]);
            *reinterpret_cast<float4*>(b + 4) = *reinterpret_cast<float4*>(&Bs[k][tx * 8 + 4]);
            #pragma unroll
            for (int i = 0; i < 8; i++)
                #pragma unroll
                for (int j = 0; j < 8; j++)
                    acc[i][j] += a[i] * b[j];
        }
        __syncthreads();
    }

    float csq[8];
    #pragma unroll
    for (int i = 0; i < 8; i++) csq[i] = g_csq[v0 + ty * 8 + i];

    #pragma unroll
    for (int j = 0; j < 8; j++) {
        int n = n0 + tx * 8 + j;
        float zs = g_zsq[n];
        unsigned long long best = ~0ull;
        #pragma unroll
        for (int i = 0; i < 8; i++) {
            // exact replication of ref: fl(fl(zs+csq) - fl(2*dot)); *2 exact
            float d = (zs + csq[i]) - 2.0f * acc[i][j];
            unsigned long long key =
                ((unsigned long long)f2ord(d) << 32) | (unsigned int)(v0 + ty * 8 + i);
            best = key < best ? key : best;
        }
        atomicMin(&red[tx * 8 + j], best);
    }
    __syncthreads();
    if (t < 128) atomicMin(&g_packed[n0 + t], red[t]);
}

// ---------------------------------------------------------------------------
// Extract tokens (and write token output as float)
// ---------------------------------------------------------------------------
__global__ void k_tokens(float* __restrict__ tok_out) {
    int n = blockIdx.x * 256 + threadIdx.x;
    int tok = (int)(g_packed[n] & 0xFFFFFFFFull);
    g_tok[n] = tok;
    tok_out[n] = (float)tok;
}

// ---------------------------------------------------------------------------
// Gather zq = codebook[token] into [img][e][hw] layout (coalesced writes)
// ---------------------------------------------------------------------------
__global__ void k_zq(const float* __restrict__ cb, float* __restrict__ zq) {
    unsigned int g = blockIdx.x * 256 + threadIdx.x;   // < 8388608
    int hw  = g & 255;
    int e   = (g >> 8) & 255;
    int img = g >> 16;
    int n = img * 256 + hw;
    zq[g] = cb[g_tok[n] * 256 + e];
}

// ---------------------------------------------------------------------------
extern "C" void kernel_launch(void* const* d_in, const int* in_sizes, int n_in,
                              void* d_out, int out_size) {
    const float* x      = (const float*)d_in[0];
    const float* cb     = (const float*)d_in[1];
    const float* pre_w  = (const float*)d_in[2];
    const float* pre_b  = (const float*)d_in[3];
    const float* post_w = (const float*)d_in[4];
    const float* post_b = (const float*)d_in[5];

    float* out   = (float*)d_out;
    float* z     = out;
    float* zq    = out + 8388608;
    float* recon = out + 16777216;
    float* toks  = out + 25165824;

    k_init<<<1024, 128>>>(cb);
    k_gemm256<true><<<dim3(4, 4, IMGS), 256>>>(pre_w, pre_b, x, z);
    k_zsq<<<IMGS, 256>>>(z);
    k_dist<<<dim3(NPIX / 128, VOCAB / 128), 256>>>(cb, z);
    k_tokens<<<NPIX / 256, 256>>>(toks);
    k_zq<<<8388608 / 256, 256>>>(cb, zq);
    k_gemm256<false><<<dim3(4, 4, IMGS), 256>>>(post_w, post_b, zq, recon);
}